// round 17
// baseline (speedup 1.0000x reference)
#include <cuda_runtime.h>
#include <cuda_bf16.h>

static constexpr int M_GT = 64;
static constexpr int BLOCK = 128;
#define TH (1.0f / 3.0f)   // iou >= 0.5  <=>  u = inter/S >= 1/3

__global__ void __launch_bounds__(BLOCK, 12)
roihead_kernel(const float4* __restrict__ proposals,   // [B, N] float4
               const float4* __restrict__ gt_boxes,    // [B, 64] float4
               const float4* __restrict__ deltas,      // [B, N] float4
               float4* __restrict__ out_decoded,
               float4* __restrict__ out_targets,
               float*  __restrict__ out_matches,
               int N)
{
    // SoA gt tile: indexed gathers hit 4 independent LDS.32 (mod-32 conflicts)
    // instead of one LDS.128 (mod-8 conflicts).
    __shared__ float s_gx[M_GT], s_gy[M_GT], s_gz[M_GT], s_gw[M_GT];
    __shared__ unsigned long long s_mask[64];   // 8x8 grid, 128px cells

    const int b = blockIdx.y;
    const int tid = threadIdx.x;

    // Prologue: load gt boxes (SoA), zero masks, rasterize.
    if (tid < M_GT) {
        s_mask[tid] = 0ull;
        float4 g = gt_boxes[b * M_GT + tid];
        s_gx[tid] = g.x; s_gy[tid] = g.y; s_gz[tid] = g.z; s_gw[tid] = g.w;
    }
    __syncthreads();

    if (tid < M_GT) {
        const float gx1 = s_gx[tid], gy1 = s_gy[tid], gx2 = s_gz[tid], gy2 = s_gw[tid];
        const int cx1 = max(0, min(7, (int)gx1 >> 7));
        const int cx2 = max(0, min(7, (int)gx2 >> 7));
        const int cy1 = max(0, min(7, (int)gy1 >> 7));
        const int cy2 = max(0, min(7, (int)gy2 >> 7));
        const unsigned long long bit = 1ull << tid;
        for (int cy = cy1; cy <= cy2; ++cy)
            for (int cx = cx1; cx <= cx2; ++cx)
                atomicOr(&s_mask[cy * 8 + cx], bit);
    }
    __syncthreads();

    const int n = blockIdx.x * BLOCK + tid;
    if (n >= N) return;
    const int idx = b * N + n;

    const float4 p = proposals[idx];
    const float areap = (p.z - p.x) * (p.w - p.y);

    // Candidate mask: static 3x3 clamped OR (boxes <= 200px span <= 3 cells/dim).
    // Two accumulators shorten the OR dependency chain.
    const int cx1 = max(0, min(7, (int)p.x >> 7));
    const int cx2 = max(0, min(7, (int)p.z >> 7));
    const int cy1 = max(0, min(7, (int)p.y >> 7));
    const int cy2 = max(0, min(7, (int)p.w >> 7));
    unsigned long long mA = 0ull, mB = 0ull;
#pragma unroll
    for (int dy = 0; dy < 3; ++dy) {
        const int cy = min(cy1 + dy, cy2);
        const int r  = cy * 8;
        mA |= s_mask[r + cx1];
        mB |= s_mask[r + min(cx1 + 1, cx2)];
        mA |= s_mask[r + min(cx1 + 2, cx2)];
    }
    unsigned long long mask = mA | mB;

    // Exact first-max argmax over candidates, 2 per trip (self-neutralizing
    // duplicate when odd count — proven R16). Excluded gts are disjoint
    // (iou==0) and output-invariant (proven R14).
    float best = -1.0f;
    int   bi   = 0;
    while (mask) {
        const int ga = __ffsll((long long)mask) - 1;
        mask &= mask - 1;
        const int gb = mask ? (__ffsll((long long)mask) - 1) : ga;
        mask &= mask - 1;   // 0 stays 0

        const float ax1 = s_gx[ga], ay1 = s_gy[ga], ax2 = s_gz[ga], ay2 = s_gw[ga];
        const float bx1 = s_gx[gb], by1 = s_gy[gb], bx2 = s_gz[gb], by2 = s_gw[gb];

        const float areaA = (ax2 - ax1) * (ay2 - ay1);   // fma pipe, replaces conflicted LDS
        const float areaB = (bx2 - bx1) * (by2 - by1);

        const float iwa = fminf(ax2, p.z) - fmaxf(ax1, p.x);   // unclamped (safe, R4)
        const float iha = fmaxf(fminf(ay2, p.w) - fmaxf(ay1, p.y), 0.0f);
        const float ua  = __fdividef(iwa * iha, areaA + areap);

        const float iwb = fminf(bx2, p.z) - fmaxf(bx1, p.x);
        const float ihb = fmaxf(fminf(by2, p.w) - fmaxf(by1, p.y), 0.0f);
        const float ub  = __fdividef(iwb * ihb, areaB + areap);

        bi   = (ua > best) ? ga : bi;    // a first (ascending g -> first-max)
        best = fmaxf(best, ua);
        bi   = (ub > best) ? gb : bi;
        best = fmaxf(best, ub);
    }

    const int match = (best >= TH) ? bi : -1;   // u >= 1/3 <=> iou >= 0.5

    // ---- Encode + decode epilogue ----
    const float aw = p.z - p.x, ah = p.w - p.y;
    const float ax = p.x + 0.5f * aw, ay = p.y + 0.5f * ah;
    const float raw = __fdividef(1.0f, aw), rah = __fdividef(1.0f, ah);

    const int  mi  = match < 0 ? 0 : match;
    const float mx1 = s_gx[mi], my1 = s_gy[mi], mx2 = s_gz[mi], my2 = s_gw[mi];
    const float gw  = fmaxf(mx2 - mx1, 1.0f);
    const float gh  = fmaxf(my2 - my1, 1.0f);
    const float gx  = mx1 + 0.5f * gw, gy = my1 + 0.5f * gh;

    float4 tgt;
    tgt.x = (gx - ax) * raw * 10.0f;
    tgt.y = (gy - ay) * rah * 10.0f;
    tgt.z = __logf(gw * raw) * 5.0f;
    tgt.w = __logf(gh * rah) * 5.0f;

    const float4 d = deltas[idx];
    const float cx = ax + (d.x * 0.1f) * aw;
    const float cy = ay + (d.y * 0.1f) * ah;
    const float ww = __expf(d.z * 0.2f) * aw;
    const float hh = __expf(d.w * 0.2f) * ah;

    float4 dec;
    dec.x = cx - 0.5f * ww;
    dec.y = cy - 0.5f * hh;
    dec.z = cx + 0.5f * ww;
    dec.w = cy + 0.5f * hh;

    out_decoded[idx] = dec;
    out_targets[idx] = tgt;
    out_matches[idx] = (float)match;
}

extern "C" void kernel_launch(void* const* d_in, const int* in_sizes, int n_in,
                              void* d_out, int out_size)
{
    const float4* proposals = (const float4*)d_in[0];
    const float4* gt_boxes  = (const float4*)d_in[1];
    const float4* deltas    = (const float4*)d_in[2];

    const int B = in_sizes[1] / (M_GT * 4);
    const int N = in_sizes[0] / (B * 4);

    float* out = (float*)d_out;
    float4* out_decoded = (float4*)out;
    float4* out_targets = (float4*)(out + (long)B * N * 4);
    float*  out_matches = out + 2L * B * N * 4;

    dim3 grid((N + BLOCK - 1) / BLOCK, B);   // one thread per proposal
    roihead_kernel<<<grid, BLOCK>>>(proposals, gt_boxes, deltas,
                                    out_decoded, out_targets, out_matches, N);
}